// round 13
// baseline (speedup 1.0000x reference)
#include <cuda_runtime.h>
#include <math.h>

#define MAX_IN 64
#define D_MODEL 64
#define ROWS_PER_BLOCK 16
#define THREADS 256
#define CAP 1024                 // rows per bucket
#define BUCKETS 64
#define BPB (CAP / ROWS_PER_BLOCK)          // 64 blocks per bucket
#define BUCKET_GRID (BUCKETS * BPB)         // 4096
#define OVF_BLOCKS 64
#define MAXN (1 << 17)

__device__ int g_bucket[BUCKETS * CAP];
__device__ int g_meta[BUCKETS + 2];   // [1..64] = per-length counts, [65] = overflow count
__device__ int g_overflow[MAXN];

__device__ __forceinline__ float fast_tanh(float x) {
    float y;
    asm("tanh.approx.f32 %0, %1;" : "=f"(y) : "f"(x));
    return y;
}

__device__ __forceinline__ float gelu_tanh(float v) {
    const float c = 0.7978845608028654f;
    float u = c * (v + 0.044715f * v * v * v);
    return 0.5f * v * (1.0f + fast_tanh(u));
}

// ---------- prepass: fused hist + range-reserve + scatter ----------
__global__ void k_scatter(const int* __restrict__ lengths, int n) {
    __shared__ int h[BUCKETS + 1];
    __shared__ int bbase[BUCKETS + 1];
    int tid = threadIdx.x;
    if (tid <= BUCKETS) h[tid] = 0;
    __syncthreads();
    int r = blockIdx.x * blockDim.x + tid;
    int len = 0, rank = 0;
    if (r < n) {
        len = lengths[r];
        len = max(1, min(64, len));
        rank = atomicAdd(&h[len], 1);
    }
    __syncthreads();
    if (tid <= BUCKETS && h[tid] > 0) bbase[tid] = atomicAdd(&g_meta[tid], h[tid]);
    __syncthreads();
    if (r < n) {
        int pos = bbase[len] + rank;
        if (pos < CAP) {
            g_bucket[(len - 1) * CAP + pos] = r;
        } else {
            int o = atomicAdd(&g_meta[BUCKETS + 1], 1);
            g_overflow[o] = r;
        }
    }
}

// ---------- row compute: padded unroll-4 loop (masked x, no tail) ----------
__device__ __forceinline__ void compute_row(
    const float* __restrict__ W, const float* __restrict__ b,
    float* __restrict__ out, const float* xr, int src, int len, int t)
{
    const int len4 = (len + 3) & ~3;
    const float4* Wr = reinterpret_cast<const float4*>(W) + (size_t)src * 1024 + t;

    float4 acc = make_float4(0.f, 0.f, 0.f, 0.f);
    #pragma unroll 1
    for (int i = 0; i < len4; i += 4) {
        float4 w0 = Wr[(i + 0) * 16];
        float4 w1 = Wr[(i + 1) * 16];
        float4 w2 = Wr[(i + 2) * 16];
        float4 w3 = Wr[(i + 3) * 16];
        float4 xv = *reinterpret_cast<const float4*>(xr + i);
        acc.x += xv.x * w0.x + xv.y * w1.x + xv.z * w2.x + xv.w * w3.x;
        acc.y += xv.x * w0.y + xv.y * w1.y + xv.z * w2.y + xv.w * w3.y;
        acc.z += xv.x * w0.z + xv.y * w1.z + xv.z * w2.z + xv.w * w3.z;
        acc.w += xv.x * w0.w + xv.y * w1.w + xv.z * w2.w + xv.w * w3.w;
    }

    float4 bb = reinterpret_cast<const float4*>(b)[(size_t)src * 16 + t];
    float4 r4;
    r4.x = gelu_tanh(acc.x + bb.x);
    r4.y = gelu_tanh(acc.y + bb.y);
    r4.z = gelu_tanh(acc.z + bb.z);
    r4.w = gelu_tanh(acc.w + bb.w);
    reinterpret_cast<float4*>(out)[(size_t)src * 16 + t] = r4;
}

// ---------- main kernel: length-homogeneous blocks, padded loop ----------
__global__ __launch_bounds__(THREADS, 6)
void fe_kernel(const float* __restrict__ seg,
               const float* __restrict__ W,
               const float* __restrict__ b,
               const int*   __restrict__ lengths,
               float* __restrict__ out,
               int n)
{
    __shared__ float sx[ROWS_PER_BLOCK][MAX_IN];
    __shared__ int   slen[ROWS_PER_BLOCK];
    __shared__ int   sidx[ROWS_PER_BLOCK];

    const int tid = threadIdx.x;

    // bucket blocks: bucket 0 = len 64 (longest first -> clean tail wave)
    {
        int bucket = blockIdx.x >> 6;
        int slot   = blockIdx.x & 63;
        int len    = BUCKETS - bucket;
        int cnt    = min(g_meta[len], CAP);
        int start  = slot * ROWS_PER_BLOCK;
        if (start >= cnt) return;
        if (tid < ROWS_PER_BLOCK) {
            int r = start + tid;
            if (r < cnt) {
                sidx[tid] = g_bucket[(len - 1) * CAP + r];
                slen[tid] = len;
            } else {
                sidx[tid] = 0;
                slen[tid] = 0;
            }
        }
    }
    __syncthreads();

    // Cooperative masked load of x rows into smem (padded loop needs zeros)
    {
        int r  = tid >> 4;
        int c4 = tid & 15;
        float4 v = make_float4(0.f, 0.f, 0.f, 0.f);
        int len = slen[r];
        if (len > 0) {
            v = reinterpret_cast<const float4*>(seg)[(size_t)sidx[r] * 16 + c4];
            int c = c4 * 4;
            if (c + 0 >= len) v.x = 0.f;
            if (c + 1 >= len) v.y = 0.f;
            if (c + 2 >= len) v.z = 0.f;
            if (c + 3 >= len) v.w = 0.f;
        }
        *reinterpret_cast<float4*>(&sx[r][c4 * 4]) = v;
    }
    __syncthreads();

    const int g = tid >> 4;
    const int t = tid & 15;
    const int len = slen[g];
    if (len == 0) return;

    compute_row(W, b, out, sx[g], sidx[g], len, t);
}

// ---------- overflow kernel: 64 grid-striding blocks (normally no work) ----------
__global__ __launch_bounds__(THREADS, 6)
void fe_overflow(const float* __restrict__ seg,
                 const float* __restrict__ W,
                 const float* __restrict__ b,
                 const int*   __restrict__ lengths,
                 float* __restrict__ out)
{
    __shared__ float sx[ROWS_PER_BLOCK][MAX_IN];
    __shared__ int   slen[ROWS_PER_BLOCK];
    __shared__ int   sidx[ROWS_PER_BLOCK];

    const int tid = threadIdx.x;
    const int cnt = g_meta[BUCKETS + 1];
    if (cnt == 0) return;

    for (int start = blockIdx.x * ROWS_PER_BLOCK; start < cnt;
         start += gridDim.x * ROWS_PER_BLOCK) {

        if (tid < ROWS_PER_BLOCK) {
            int r = start + tid;
            if (r < cnt) {
                int src = g_overflow[r];
                sidx[tid] = src;
                slen[tid] = lengths[src];
            } else {
                sidx[tid] = 0;
                slen[tid] = 0;
            }
        }
        __syncthreads();
        {
            int r  = tid >> 4;
            int c4 = tid & 15;
            float4 v = make_float4(0.f, 0.f, 0.f, 0.f);
            int len = slen[r];
            if (len > 0) {
                v = reinterpret_cast<const float4*>(seg)[(size_t)sidx[r] * 16 + c4];
                int c = c4 * 4;
                if (c + 0 >= len) v.x = 0.f;
                if (c + 1 >= len) v.y = 0.f;
                if (c + 2 >= len) v.z = 0.f;
                if (c + 3 >= len) v.w = 0.f;
            }
            *reinterpret_cast<float4*>(&sx[r][c4 * 4]) = v;
        }
        __syncthreads();

        const int g = tid >> 4;
        const int t = tid & 15;
        const int len = slen[g];
        if (len > 0) compute_row(W, b, out, sx[g], sidx[g], len, t);
        __syncthreads();
    }
}

// ---------- fallback for n > MAXN (defensive; not hit at N=50000) ----------
__global__ __launch_bounds__(THREADS, 6)
void fe_plain(const float* __restrict__ seg,
              const float* __restrict__ W,
              const float* __restrict__ b,
              const int*   __restrict__ lengths,
              float* __restrict__ out,
              int n)
{
    __shared__ float sx[ROWS_PER_BLOCK][MAX_IN];
    __shared__ int   slen[ROWS_PER_BLOCK];

    const int row0 = blockIdx.x * ROWS_PER_BLOCK;
    const int tid  = threadIdx.x;

    if (tid < ROWS_PER_BLOCK) {
        int r = row0 + tid;
        slen[tid] = (r < n) ? lengths[r] : 0;
    }
    __syncthreads();
    {
        int r  = tid >> 4;
        int c4 = tid & 15;
        float4 v = make_float4(0.f, 0.f, 0.f, 0.f);
        int len = slen[r];
        if (len > 0) {
            v = reinterpret_cast<const float4*>(seg)[(size_t)(row0 + r) * 16 + c4];
            int c = c4 * 4;
            if (c + 0 >= len) v.x = 0.f;
            if (c + 1 >= len) v.y = 0.f;
            if (c + 2 >= len) v.z = 0.f;
            if (c + 3 >= len) v.w = 0.f;
        }
        *reinterpret_cast<float4*>(&sx[r][c4 * 4]) = v;
    }
    __syncthreads();

    const int g = tid >> 4;
    const int t = tid & 15;
    const int row = row0 + g;
    if (row >= n || slen[g] == 0) return;

    compute_row(W, b, out, sx[g], row, slen[g], t);
}

extern "C" void kernel_launch(void* const* d_in, const int* in_sizes, int n_in,
                              void* d_out, int out_size) {
    const float* seg     = (const float*)d_in[0];
    const float* W       = (const float*)d_in[1];
    const float* b       = (const float*)d_in[2];
    const int*   lengths = (const int*)d_in[3];
    float* out = (float*)d_out;

    int n = in_sizes[3];

    if (n <= MAXN) {
        void* meta_ptr = nullptr;
        cudaGetSymbolAddress(&meta_ptr, g_meta);
        cudaMemsetAsync(meta_ptr, 0, sizeof(int) * (BUCKETS + 2));

        int sgrid = (n + THREADS - 1) / THREADS;
        k_scatter<<<sgrid, THREADS>>>(lengths, n);
        fe_kernel<<<BUCKET_GRID, THREADS>>>(seg, W, b, lengths, out, n);
        fe_overflow<<<OVF_BLOCKS, THREADS>>>(seg, W, b, lengths, out);
    } else {
        int grid = (n + ROWS_PER_BLOCK - 1) / ROWS_PER_BLOCK;
        fe_plain<<<grid, THREADS>>>(seg, W, b, lengths, out, n);
    }
}